// round 6
// baseline (speedup 1.0000x reference)
#include <cuda_runtime.h>

#define NBLK    444            // 148 SMs x 3 resident CTAs
#define NTHR    512            // 1536 threads/SM -> 48 warps/SM (~75% occ)

// Scratch (no allocations). State overwritten each run, wraps (g_count), or is
// monotonic with entry-captured baseline (g_epoch) -> graph-replay safe.
__device__ double                g_partials[NBLK];
__device__ float                 g_total;
__device__ unsigned int          g_count;
__device__ volatile unsigned int g_epoch;

__global__ void __launch_bounds__(NTHR, 3) fused_kernel(const float4* __restrict__ x4,
                                                        float4* __restrict__ out4,
                                                        long long n4)
{
    const long long tid    = (long long)blockIdx.x * blockDim.x + threadIdx.x;
    const long long stride = (long long)gridDim.x * blockDim.x;

    // Capture epoch BEFORE any work: bumper fires only after all CTAs arrive.
    const unsigned epoch0 = g_epoch;

    // -------- Phase 1: ascending reduction, 4 independent float4 streams ----
    float s0=0.f, s1=0.f, s2=0.f, s3=0.f;

    long long i = tid;
    for (; i + 3*stride < n4; i += 4*stride) {
        float4 v0 = x4[i];
        float4 v1 = x4[i +   stride];
        float4 v2 = x4[i + 2*stride];
        float4 v3 = x4[i + 3*stride];
        s0 += (v0.x + v0.y) + (v0.z + v0.w);
        s1 += (v1.x + v1.y) + (v1.z + v1.w);
        s2 += (v2.x + v2.y) + (v2.z + v2.w);
        s3 += (v3.x + v3.y) + (v3.z + v3.w);
    }
    for (; i < n4; i += stride) {
        float4 v = x4[i];
        s0 += (v.x + v.y) + (v.z + v.w);
    }

    double acc = ((double)s0 + (double)s1) + ((double)s2 + (double)s3);

    __shared__ double sdata[NTHR];
    sdata[threadIdx.x] = acc;
    __syncthreads();
    for (int s = NTHR/2; s > 0; s >>= 1) {
        if (threadIdx.x < s) sdata[threadIdx.x] += sdata[threadIdx.x + s];
        __syncthreads();
    }

    // -------- Arrival + last-block finalize ---------------------------------
    __shared__ bool s_isLast;
    if (threadIdx.x == 0) {
        g_partials[blockIdx.x] = sdata[0];
        __threadfence();
        unsigned v = atomicInc(&g_count, gridDim.x - 1);   // wraps -> replay-safe
        s_isLast = (v == gridDim.x - 1);
    }
    __syncthreads();

    if (s_isLast) {
        double facc = 0.0;
        for (int k = threadIdx.x; k < NBLK; k += NTHR) facc += g_partials[k];
        sdata[threadIdx.x] = facc;
        __syncthreads();
        for (int s = NTHR/2; s > 0; s >>= 1) {
            if (threadIdx.x < s) sdata[threadIdx.x] += sdata[threadIdx.x + s];
            __syncthreads();
        }
        if (threadIdx.x == 0) {
            float  sf = (float)sdata[0];        // mimic jnp.sum's fp32 result
            double nn = trunc((double)sf);
            double tt = (nn > 1.0) ? nn * (nn - 1.0) * 0.5 : 0.0;
            g_total = (float)tt;
            __threadfence();
            g_epoch = g_epoch + 1;              // release
        }
        __syncthreads();
    } else {
        if (threadIdx.x == 0) {
            while (g_epoch == epoch0) { __nanosleep(64); }
            __threadfence();
        }
        __syncthreads();
    }

    __shared__ float s_t;
    if (threadIdx.x == 0) s_t = g_total;
    __syncthreads();
    const float t = s_t;

    // -------- Phase 2: out = x + t, DESCENDING over this thread's own
    //          phase-1 index set (first reads hit the L2 lines this SM pulled
    //          at the end of phase 1). 2-way unroll to stay under the 42-reg
    //          cap; warp-level MLP (48 warps/SM) supplies the rest. ----------
    long long iters = (n4 - 1 - tid) / stride + 1;     // tid < n4 always here
    long long j = tid + (iters - 1) * stride;

    for (; iters >= 2; iters -= 2, j -= 2*stride) {
        float4 a = __ldcs(&x4[j]);
        float4 b = __ldcs(&x4[j - stride]);
        a.x += t; a.y += t; a.z += t; a.w += t;
        b.x += t; b.y += t; b.z += t; b.w += t;
        __stcs(&out4[j],          a);
        __stcs(&out4[j - stride], b);
    }
    if (iters > 0) {
        float4 a = __ldcs(&x4[j]);
        a.x += t; a.y += t; a.z += t; a.w += t;
        __stcs(&out4[j], a);
    }
}

extern "C" void kernel_launch(void* const* d_in, const int* in_sizes, int n_in,
                              void* d_out, int out_size)
{
    const float4* x4   = (const float4*)d_in[0];
    float4*       out4 = (float4*)d_out;
    long long n  = (long long)in_sizes[0];   // 8192*8192
    long long n4 = n >> 2;

    fused_kernel<<<NBLK, NTHR>>>(x4, out4, n4);
}

// round 7
// speedup vs baseline: 1.0288x; 1.0288x over previous
#include <cuda_runtime.h>

#define NBLK 296               // 148 SMs x 2 resident CTAs (R5's best config)
#define NTHR 512
#define CHUNK 2048LL           // float4 per chunk = 32 KB

// Scratch (no allocations). State overwritten each run, wraps (g_count), or is
// monotonic with entry-captured baseline (g_epoch) -> graph-replay safe.
__device__ double                g_partials[NBLK];
__device__ float                 g_total;
__device__ unsigned int          g_count;
__device__ volatile unsigned int g_epoch;

__global__ void __launch_bounds__(NTHR, 2) fused_kernel(const float4* __restrict__ x4,
                                                        float4* __restrict__ out4,
                                                        long long n4)
{
    const long long nch     = n4 / CHUNK;          // 8192 for 8192^2
    const long long n4_main = nch * CHUNK;
    const long long tid     = (long long)blockIdx.x * blockDim.x + threadIdx.x;
    const long long gstride = (long long)gridDim.x * blockDim.x;

    // Capture epoch BEFORE any work: bumper fires only after all CTAs arrive.
    const unsigned epoch0 = g_epoch;

    // -------- Phase 1: reduction, chunks walked DESCENDING ------------------
    // Each CTA-iteration reads one contiguous 32KB chunk (4 coalesced float4
    // per thread). Last lines touched chip-wide = lowest addresses -> they sit
    // in L2 when phase 2 begins.
    float s0=0.f, s1=0.f, s2=0.f, s3=0.f;

    for (long long c = nch - 1 - blockIdx.x; c >= 0; c -= NBLK) {
        const float4* base = x4 + c * CHUNK + threadIdx.x;
        float4 v0 = base[0];
        float4 v1 = base[512];
        float4 v2 = base[1024];
        float4 v3 = base[1536];
        s0 += (v0.x + v0.y) + (v0.z + v0.w);
        s1 += (v1.x + v1.y) + (v1.z + v1.w);
        s2 += (v2.x + v2.y) + (v2.z + v2.w);
        s3 += (v3.x + v3.y) + (v3.z + v3.w);
    }
    // Generic tail (empty for 8192^2)
    for (long long i = n4_main + tid; i < n4; i += gstride) {
        float4 v = x4[i];
        s0 += (v.x + v.y) + (v.z + v.w);
    }

    double acc = ((double)s0 + (double)s1) + ((double)s2 + (double)s3);

    __shared__ double sdata[NTHR];
    sdata[threadIdx.x] = acc;
    __syncthreads();
    for (int s = NTHR/2; s > 0; s >>= 1) {
        if (threadIdx.x < s) sdata[threadIdx.x] += sdata[threadIdx.x + s];
        __syncthreads();
    }

    // -------- Arrival + last-block finalize ---------------------------------
    __shared__ bool s_isLast;
    if (threadIdx.x == 0) {
        g_partials[blockIdx.x] = sdata[0];
        __threadfence();
        unsigned v = atomicInc(&g_count, gridDim.x - 1);   // wraps -> replay-safe
        s_isLast = (v == gridDim.x - 1);
    }
    __syncthreads();

    if (s_isLast) {
        double facc = 0.0;
        for (int k = threadIdx.x; k < NBLK; k += NTHR) facc += g_partials[k];
        sdata[threadIdx.x] = facc;
        __syncthreads();
        for (int s = NTHR/2; s > 0; s >>= 1) {
            if (threadIdx.x < s) sdata[threadIdx.x] += sdata[threadIdx.x + s];
            __syncthreads();
        }
        if (threadIdx.x == 0) {
            float  sf = (float)sdata[0];        // mimic jnp.sum's fp32 result
            double nn = trunc((double)sf);
            double tt = (nn > 1.0) ? nn * (nn - 1.0) * 0.5 : 0.0;
            g_total = (float)tt;
            __threadfence();
            g_epoch = g_epoch + 1;              // release
        }
        __syncthreads();
    } else {
        if (threadIdx.x == 0) {
            while (g_epoch == epoch0) { __nanosleep(64); }
            __threadfence();
        }
        __syncthreads();
    }

    __shared__ float s_t;
    if (threadIdx.x == 0) s_t = g_total;
    __syncthreads();
    const float t = s_t;

    // -------- Phase 2: out = x + t, chunks walked ASCENDING -----------------
    // First reads hit the low-address L2 residue phase 1 just left, then
    // transition to clean ascending DRAM streaming. __stcs writes bypass
    // residency; __ldcs reads don't pollute.
    for (long long c = blockIdx.x; c < nch; c += NBLK) {
        const float4* src = x4   + c * CHUNK + threadIdx.x;
        float4*       dst = out4 + c * CHUNK + threadIdx.x;
        float4 v0 = __ldcs(src);
        float4 v1 = __ldcs(src + 512);
        float4 v2 = __ldcs(src + 1024);
        float4 v3 = __ldcs(src + 1536);
        v0.x += t; v0.y += t; v0.z += t; v0.w += t;
        v1.x += t; v1.y += t; v1.z += t; v1.w += t;
        v2.x += t; v2.y += t; v2.z += t; v2.w += t;
        v3.x += t; v3.y += t; v3.z += t; v3.w += t;
        __stcs(dst,        v0);
        __stcs(dst + 512,  v1);
        __stcs(dst + 1024, v2);
        __stcs(dst + 1536, v3);
    }
    // Generic tail (empty for 8192^2)
    for (long long i = n4_main + tid; i < n4; i += gstride) {
        float4 v = __ldcs(&x4[i]);
        v.x += t; v.y += t; v.z += t; v.w += t;
        __stcs(&out4[i], v);
    }
}

extern "C" void kernel_launch(void* const* d_in, const int* in_sizes, int n_in,
                              void* d_out, int out_size)
{
    const float4* x4   = (const float4*)d_in[0];
    float4*       out4 = (float4*)d_out;
    long long n  = (long long)in_sizes[0];   // 8192*8192
    long long n4 = n >> 2;

    fused_kernel<<<NBLK, NTHR>>>(x4, out4, n4);
}